// round 2
// baseline (speedup 1.0000x reference)
#include <cuda_runtime.h>

#define NN 50000
#define EE 800000
#define GG 128
#define FIN 16
#define HH 64
#define LL 63

// ---------------- scratch (device globals; no allocations) ----------------
__device__ __align__(16) float g_agg1[NN * FIN];
__device__ __align__(16) float g_h1[NN * HH];
__device__ __align__(16) float g_agg2[NN * HH];
__device__ float g_s[NN];
__device__ float g_poolS[GG];
__device__ float g_poolT[GG];
__device__ float g_cnt[GG];
__device__ float g_urel[HH];
__device__ float g_uroot[HH];
__device__ float g_e;

// Vectorized no-return global float reduction (sm_90+)
__device__ __forceinline__ void red4(float* p, float4 v) {
    asm volatile("red.global.add.v4.f32 [%0], {%1,%2,%3,%4};"
                 :: "l"(p), "f"(v.x), "f"(v.y), "f"(v.z), "f"(v.w)
                 : "memory");
}

// ---------------- zero scratch ----------------
__global__ void k_zero() {
    int i = blockIdx.x * 256 + threadIdx.x;
    if (i < NN * FIN) g_agg1[i] = 0.f;
    if (i < NN * HH)  g_agg2[i] = 0.f;
    if (i < GG) { g_poolS[i] = 0.f; g_poolT[i] = 0.f; g_cnt[i] = 0.f; }
}

// ---------------- fold the 63 Conv1d layers + GraphConv3 weights ----------------
// scalar(h3) = c . h3 + d   (c,d from the affine chain)
// c.(agg2@Wrel3 + b3 + h2@Wroot3) = agg2.(Wrel3 c) + h2.(Wroot3 c) + (b3.c)
__global__ void k_coeffs(const float* __restrict__ w, const float* __restrict__ b,
                         const float* __restrict__ Wrel3, const float* __restrict__ brel3,
                         const float* __restrict__ Wroot3) {
    __shared__ float a[HH];
    __shared__ float dsh;
    if (threadIdx.x == 0) {
        float c[HH];
        c[0] = 1.f;
        int len = 1;
        float d = 0.f;
        for (int i = LL - 1; i >= 0; --i) {
            float w0 = w[2 * i], w1 = w[2 * i + 1];
            float sum = 0.f;
            for (int j = 0; j < len; j++) sum += c[j];
            d += b[i] * sum;
            c[len] = w1 * c[len - 1];
            for (int j = len - 1; j >= 1; --j) c[j] = w0 * c[j] + w1 * c[j - 1];
            c[0] = w0 * c[0];
            len++;
        }
        for (int j = 0; j < HH; j++) a[j] = c[j];
        dsh = d;
    }
    __syncthreads();
    int j = threadIdx.x;  // 64 threads
    float ur = 0.f, uo = 0.f;
    for (int k = 0; k < HH; k++) {
        ur += Wrel3[j * HH + k] * a[k];
        uo += Wroot3[j * HH + k] * a[k];
    }
    g_urel[j] = ur;
    g_uroot[j] = uo;
    if (j == 0) {
        float e = dsh;
        for (int k = 0; k < HH; k++) e += brel3[k] * a[k];
        g_e = e;
    }
}

// ---------------- edge scatter 1: agg1[dst] += x[src]  (16 feats) ----------------
__global__ void __launch_bounds__(256) k_scatter1(const int* __restrict__ ei,
                                                  const float* __restrict__ x) {
    int t = blockIdx.x * 256 + threadIdx.x;  // EE*4 threads
    int e = t >> 2, q = t & 3;
    int src = ei[e];
    int dst = ei[EE + e];
    float4 v = reinterpret_cast<const float4*>(x + (size_t)src * FIN)[q];
    red4(&g_agg1[(size_t)dst * FIN + q * 4], v);
}

// ---------------- GraphConv 1: h1 = relu(agg1@Wrel1 + b1 + x@Wroot1) ----------------
// 64 threads, 16 nodes/block, 4x4 register tile per thread
#define S1 20  // padded row stride (floats) for 16-wide staging (5 float4)
__global__ void __launch_bounds__(64) k_gc1(const float* __restrict__ x,
                                            const float* __restrict__ Wrel,
                                            const float* __restrict__ brel,
                                            const float* __restrict__ Wroot) {
    __shared__ float swr[FIN * HH];
    __shared__ float swo[FIN * HH];
    __shared__ float sb[HH];
    __shared__ float sa[16 * S1];
    __shared__ float sx[16 * S1];
    int t = threadIdx.x;
    {
        const float4* wr4 = (const float4*)Wrel;
        const float4* wo4 = (const float4*)Wroot;
        float4* swr4 = (float4*)swr;
        float4* swo4 = (float4*)swo;
        #pragma unroll
        for (int i = t; i < FIN * HH / 4; i += 64) { swr4[i] = wr4[i]; swo4[i] = wo4[i]; }
    }
    sb[t] = brel[t];
    int node0 = blockIdx.x * 16;
    {
        const float4* a4 = (const float4*)(g_agg1 + (size_t)node0 * FIN);
        const float4* x4 = (const float4*)(x + (size_t)node0 * FIN);
        float4* sa4 = (float4*)sa;
        float4* sx4 = (float4*)sx;
        // 16 nodes * 4 float4 each = 64
        int n = t >> 2, jj = t & 3;
        sa4[n * (S1 / 4) + jj] = a4[n * 4 + jj];
        sx4[n * (S1 / 4) + jj] = x4[n * 4 + jj];
    }
    __syncthreads();
    int kg = t & 15, ng = t >> 4;
    int k0 = kg * 4, n0 = ng * 4;
    float acc[4][4];
    #pragma unroll
    for (int i = 0; i < 4; i++) {
        acc[i][0] = sb[k0]; acc[i][1] = sb[k0 + 1]; acc[i][2] = sb[k0 + 2]; acc[i][3] = sb[k0 + 3];
    }
    #pragma unroll
    for (int j = 0; j < FIN; j++) {
        float4 wr = *(const float4*)&swr[j * HH + k0];
        float4 wo = *(const float4*)&swo[j * HH + k0];
        #pragma unroll
        for (int i = 0; i < 4; i++) {
            float av = sa[(n0 + i) * S1 + j];
            float xv = sx[(n0 + i) * S1 + j];
            acc[i][0] = fmaf(av, wr.x, fmaf(xv, wo.x, acc[i][0]));
            acc[i][1] = fmaf(av, wr.y, fmaf(xv, wo.y, acc[i][1]));
            acc[i][2] = fmaf(av, wr.z, fmaf(xv, wo.z, acc[i][2]));
            acc[i][3] = fmaf(av, wr.w, fmaf(xv, wo.w, acc[i][3]));
        }
    }
    #pragma unroll
    for (int i = 0; i < 4; i++) {
        float4 o;
        o.x = fmaxf(acc[i][0], 0.f);
        o.y = fmaxf(acc[i][1], 0.f);
        o.z = fmaxf(acc[i][2], 0.f);
        o.w = fmaxf(acc[i][3], 0.f);
        *(float4*)&g_h1[(size_t)(node0 + n0 + i) * HH + k0] = o;
    }
}

// ---------------- edge scatter 2: agg2[dst] += h1[src]  (64 feats) ----------------
__global__ void __launch_bounds__(256) k_scatter2(const int* __restrict__ ei) {
    int t = blockIdx.x * 256 + threadIdx.x;  // EE*16 threads
    int e = t >> 4, q = t & 15;
    int src = ei[e];
    int dst = ei[EE + e];
    float4 v = reinterpret_cast<const float4*>(g_h1 + (size_t)src * HH)[q];
    red4(&g_agg2[(size_t)dst * HH + q * 4], v);
}

// ---------------- GraphConv 2 + folded layer 3 ----------------
// h2 = relu(agg2@Wrel2 + b2 + h1@Wroot2); s = h2.u_rel; t = h2.u_root
#define S2 68  // padded row stride for 64-wide staging (17 float4)
__global__ void __launch_bounds__(64) k_gc2(const int* __restrict__ batch,
                                            const float* __restrict__ Wrel,
                                            const float* __restrict__ brel,
                                            const float* __restrict__ Wroot) {
    __shared__ float swr[HH * HH];
    __shared__ float swo[HH * HH];
    __shared__ float sb[HH], su[HH], sv[HH];
    __shared__ float sa[16 * S2];
    __shared__ float sh[16 * S2];
    int t = threadIdx.x;
    {
        const float4* wr4 = (const float4*)Wrel;
        const float4* wo4 = (const float4*)Wroot;
        float4* swr4 = (float4*)swr;
        float4* swo4 = (float4*)swo;
        #pragma unroll
        for (int i = t; i < HH * HH / 4; i += 64) { swr4[i] = wr4[i]; swo4[i] = wo4[i]; }
    }
    sb[t] = brel[t];
    su[t] = g_urel[t];
    sv[t] = g_uroot[t];
    int node0 = blockIdx.x * 16;
    {
        const float4* a4 = (const float4*)(g_agg2 + (size_t)node0 * HH);
        const float4* h4 = (const float4*)(g_h1 + (size_t)node0 * HH);
        float4* sa4 = (float4*)sa;
        float4* sh4 = (float4*)sh;
        // 16 nodes * 16 float4 each = 256 -> 4 iterations
        #pragma unroll
        for (int i = t; i < 16 * 16; i += 64) {
            int n = i >> 4, jj = i & 15;
            sa4[n * (S2 / 4) + jj] = a4[n * 16 + jj];
            sh4[n * (S2 / 4) + jj] = h4[n * 16 + jj];
        }
    }
    __syncthreads();
    int kg = t & 15, ng = t >> 4;
    int k0 = kg * 4, n0 = ng * 4;
    float acc[4][4];
    #pragma unroll
    for (int i = 0; i < 4; i++) {
        acc[i][0] = sb[k0]; acc[i][1] = sb[k0 + 1]; acc[i][2] = sb[k0 + 2]; acc[i][3] = sb[k0 + 3];
    }
    #pragma unroll 4
    for (int j = 0; j < HH; j++) {
        float4 wr = *(const float4*)&swr[j * HH + k0];
        float4 wo = *(const float4*)&swo[j * HH + k0];
        #pragma unroll
        for (int i = 0; i < 4; i++) {
            float av = sa[(n0 + i) * S2 + j];
            float hv = sh[(n0 + i) * S2 + j];
            acc[i][0] = fmaf(av, wr.x, fmaf(hv, wo.x, acc[i][0]));
            acc[i][1] = fmaf(av, wr.y, fmaf(hv, wo.y, acc[i][1]));
            acc[i][2] = fmaf(av, wr.z, fmaf(hv, wo.z, acc[i][2]));
            acc[i][3] = fmaf(av, wr.w, fmaf(hv, wo.w, acc[i][3]));
        }
    }
    float u0 = su[k0], u1 = su[k0 + 1], u2 = su[k0 + 2], u3 = su[k0 + 3];
    float v0 = sv[k0], v1 = sv[k0 + 1], v2 = sv[k0 + 2], v3 = sv[k0 + 3];
    #pragma unroll
    for (int i = 0; i < 4; i++) {
        float h0 = fmaxf(acc[i][0], 0.f);
        float h1 = fmaxf(acc[i][1], 0.f);
        float h2 = fmaxf(acc[i][2], 0.f);
        float h3 = fmaxf(acc[i][3], 0.f);
        float sp = h0 * u0 + h1 * u1 + h2 * u2 + h3 * u3;
        float tp = h0 * v0 + h1 * v1 + h2 * v2 + h3 * v3;
        #pragma unroll
        for (int off = 8; off > 0; off >>= 1) {
            sp += __shfl_down_sync(0xffffffffu, sp, off, 16);
            tp += __shfl_down_sync(0xffffffffu, tp, off, 16);
        }
        if (kg == 0) {
            int node = node0 + n0 + i;
            g_s[node] = sp;
            int g = batch[node];
            atomicAdd(&g_poolT[g], tp);
            atomicAdd(&g_cnt[g], 1.0f);
        }
    }
}

// ---------------- scalar edge scatter into per-graph pool ----------------
__global__ void __launch_bounds__(256) k_scatter3(const int* __restrict__ ei,
                                                  const int* __restrict__ batch) {
    __shared__ float bins[GG];
    int t = threadIdx.x;
    if (t < GG) bins[t] = 0.f;
    __syncthreads();
    int e = blockIdx.x * 256 + t;
    int src = ei[e];
    int dst = ei[EE + e];
    int g = batch[dst];
    atomicAdd(&bins[g], g_s[src]);
    __syncthreads();
    if (t < GG && bins[t] != 0.f) atomicAdd(&g_poolS[t], bins[t]);
}

// ---------------- finalize: mean pool ----------------
__global__ void k_finalize(float* __restrict__ out) {
    int g = threadIdx.x;
    if (g < GG) {
        float c = g_cnt[g];
        out[g] = (c > 0.f) ? (g_poolS[g] + g_poolT[g]) / c + g_e : 0.f;
    }
}

extern "C" void kernel_launch(void* const* d_in, const int* in_sizes, int n_in,
                              void* d_out, int out_size) {
    const float* x      = (const float*)d_in[0];
    const int*   ei     = (const int*)d_in[1];
    const int*   batch  = (const int*)d_in[2];
    const float* Wrel1  = (const float*)d_in[3];
    const float* brel1  = (const float*)d_in[4];
    const float* Wroot1 = (const float*)d_in[5];
    const float* Wrel2  = (const float*)d_in[6];
    const float* brel2  = (const float*)d_in[7];
    const float* Wroot2 = (const float*)d_in[8];
    const float* Wrel3  = (const float*)d_in[9];
    const float* brel3  = (const float*)d_in[10];
    const float* Wroot3 = (const float*)d_in[11];
    const float* c1w    = (const float*)d_in[12];
    const float* c1b    = (const float*)d_in[13];
    float* out = (float*)d_out;

    k_zero<<<(NN * HH) / 256, 256>>>();
    k_coeffs<<<1, 64>>>(c1w, c1b, Wrel3, brel3, Wroot3);
    k_scatter1<<<(EE * 4) / 256, 256>>>(ei, x);
    k_gc1<<<NN / 16, 64>>>(x, Wrel1, brel1, Wroot1);
    k_scatter2<<<(EE * 16) / 256, 256>>>(ei);
    k_gc2<<<NN / 16, 64>>>(batch, Wrel2, brel2, Wroot2);
    k_scatter3<<<EE / 256, 256>>>(ei, batch);
    k_finalize<<<1, 128>>>(out);
}

// round 3
// speedup vs baseline: 1.6568x; 1.6568x over previous
#include <cuda_runtime.h>

#define NN 50000
#define EE 800000
#define GG 128
#define FIN 16
#define HH 64
#define LL 63
#define GRID_GC ((NN + 63) / 64)

// ---------------- scratch (device globals; no allocations) ----------------
__device__ int g_hist[NN];
__device__ int g_off[NN + 1];
__device__ int g_cursor[NN];
__device__ int g_srt[EE];
__device__ __align__(16) float g_h1[NN * HH];
__device__ float g_s[NN];
__device__ float g_poolS[GG], g_poolT[GG];
__device__ float g_urel[HH], g_uroot[HH];
__device__ float g_e;

// ---------------- zero ----------------
__global__ void k_zero() {
    int i = blockIdx.x * 256 + threadIdx.x;
    if (i < NN) g_hist[i] = 0;
    if (i < GG) { g_poolS[i] = 0.f; g_poolT[i] = 0.f; }
}

// ---------------- histogram of dst ----------------
__global__ void __launch_bounds__(256) k_hist(const int* __restrict__ ei) {
    int e = blockIdx.x * 256 + threadIdx.x;
    atomicAdd(&g_hist[ei[EE + e]], 1);
}

// ---------------- exclusive scan -> CSR offsets (single block) ----------------
__global__ void __launch_bounds__(1024) k_scan() {
    __shared__ int part[1024];
    int t = threadIdx.x;
    const int CH = (NN + 1023) / 1024;  // 49
    int beg = t * CH;
    int end = beg + CH < NN ? beg + CH : NN;
    int s = 0;
    for (int i = beg; i < end; i++) s += g_hist[i];
    part[t] = s;
    __syncthreads();
    for (int d = 1; d < 1024; d <<= 1) {
        int v = (t >= d) ? part[t - d] : 0;
        __syncthreads();
        part[t] += v;
        __syncthreads();
    }
    int run = part[t] - s;  // exclusive prefix of this chunk
    for (int i = beg; i < end; i++) {
        g_off[i] = run;
        g_cursor[i] = run;
        run += g_hist[i];
    }
    if (t == 1023) g_off[NN] = run;
}

// ---------------- build sorted src list (counting sort by dst) ----------------
__global__ void __launch_bounds__(256) k_build(const int* __restrict__ ei) {
    int e = blockIdx.x * 256 + threadIdx.x;
    int src = ei[e];
    int dst = ei[EE + e];
    int pos = atomicAdd(&g_cursor[dst], 1);
    g_srt[pos] = src;
}

// ---------------- fold 63 Conv1d layers + GraphConv3 into (u_rel, u_root, e) ----------------
__global__ void k_coeffs(const float* __restrict__ w, const float* __restrict__ b,
                         const float* __restrict__ Wrel3, const float* __restrict__ brel3,
                         const float* __restrict__ Wroot3) {
    __shared__ float c[HH];
    __shared__ float dsh;
    int t = threadIdx.x;  // 64 threads
    c[t] = (t == 0) ? 1.f : 0.f;
    float Ssum = 1.f, dacc = 0.f;
    __syncthreads();
    for (int i = LL - 1; i >= 0; --i) {
        float w0 = w[2 * i], w1 = w[2 * i + 1];
        float prev = (t > 0) ? c[t - 1] : 0.f;
        float cur = c[t];
        __syncthreads();
        c[t] = fmaf(w0, cur, w1 * prev);
        if (t == 0) { dacc += b[i] * Ssum; Ssum = (w0 + w1) * Ssum; }
        __syncthreads();
    }
    if (t == 0) dsh = dacc;
    __syncthreads();
    float ur = 0.f, uo = 0.f;
    #pragma unroll 4
    for (int k = 0; k < HH; k++) {
        ur += Wrel3[t * HH + k] * c[k];
        uo += Wroot3[t * HH + k] * c[k];
    }
    g_urel[t] = ur;
    g_uroot[t] = uo;
    if (t == 0) {
        float e = dsh;
        for (int k = 0; k < HH; k++) e += brel3[k] * c[k];
        g_e = e;
    }
}

// ---------------- GC1 fused: agg = CSR-gather(x); h1 = relu(agg@Wrel1 + b + x@Wroot1) ----
// 256 threads, 64 nodes/block
__global__ void __launch_bounds__(256) k_gc1(const float* __restrict__ x,
                                             const float* __restrict__ Wrel,
                                             const float* __restrict__ brel,
                                             const float* __restrict__ Wroot) {
    __shared__ float swr[FIN * HH];
    __shared__ float swo[FIN * HH];
    __shared__ float sb[HH];
    __shared__ float sa[64 * 17];
    __shared__ float sx[64 * 20];
    int t = threadIdx.x;
    int node0 = blockIdx.x * 64;
    {
        const float4* wr4 = (const float4*)Wrel;
        const float4* wo4 = (const float4*)Wroot;
        float4* swr4 = (float4*)swr;
        float4* swo4 = (float4*)swo;
        if (t < FIN * HH / 4) { swr4[t] = wr4[t]; swo4[t] = wo4[t]; }
        if (t < HH) sb[t] = brel[t];
    }
    // stage root rows
    {
        float4 z = make_float4(0.f, 0.f, 0.f, 0.f);
        int r = t >> 2, q = t & 3;  // 256 = 64 rows x 4 quads
        float4 v = (node0 + r < NN) ? ((const float4*)(x + (size_t)(node0 + r) * FIN))[q] : z;
        *(float4*)&sx[r * 20 + q * 4] = v;
    }
    // gather: 8 warps x 8 nodes
    {
        int w = t >> 5, lid = t & 31;
        int col = lid & 15, half = lid >> 4;
        #pragma unroll
        for (int k = 0; k < 8; k++) {
            int ln = w * 8 + k;
            int node = node0 + ln;
            float acc = 0.f;
            if (node < NN) {
                int beg = g_off[node], end = g_off[node + 1];
                int j = beg + half;
                for (; j + 2 < end; j += 4) {
                    int s0 = g_srt[j], s1 = g_srt[j + 2];
                    acc += __ldg(&x[(size_t)s0 * FIN + col]) + __ldg(&x[(size_t)s1 * FIN + col]);
                }
                if (j < end) acc += __ldg(&x[(size_t)g_srt[j] * FIN + col]);
            }
            acc += __shfl_down_sync(0xffffffffu, acc, 16);
            if (lid < 16) sa[ln * 17 + col] = acc;
        }
    }
    __syncthreads();
    int kg = t & 15, ng = t >> 4;
    int k0 = kg * 4, n0 = ng * 4;
    float acc[4][4];
    #pragma unroll
    for (int i = 0; i < 4; i++) {
        acc[i][0] = sb[k0]; acc[i][1] = sb[k0 + 1]; acc[i][2] = sb[k0 + 2]; acc[i][3] = sb[k0 + 3];
    }
    #pragma unroll
    for (int j = 0; j < FIN; j++) {
        float4 wr = *(const float4*)&swr[j * HH + k0];
        float4 wo = *(const float4*)&swo[j * HH + k0];
        #pragma unroll
        for (int i = 0; i < 4; i++) {
            float av = sa[(n0 + i) * 17 + j];
            float xv = sx[(n0 + i) * 20 + j];
            acc[i][0] = fmaf(av, wr.x, fmaf(xv, wo.x, acc[i][0]));
            acc[i][1] = fmaf(av, wr.y, fmaf(xv, wo.y, acc[i][1]));
            acc[i][2] = fmaf(av, wr.z, fmaf(xv, wo.z, acc[i][2]));
            acc[i][3] = fmaf(av, wr.w, fmaf(xv, wo.w, acc[i][3]));
        }
    }
    #pragma unroll
    for (int i = 0; i < 4; i++) {
        int node = node0 + n0 + i;
        if (node < NN) {
            float4 o;
            o.x = fmaxf(acc[i][0], 0.f);
            o.y = fmaxf(acc[i][1], 0.f);
            o.z = fmaxf(acc[i][2], 0.f);
            o.w = fmaxf(acc[i][3], 0.f);
            *(float4*)&g_h1[(size_t)node * HH + k0] = o;
        }
    }
}

// ---------------- GC2 fused (two-pass shared buffer) + folded layer 3 -------------
// h2 = relu(agg2@Wrel2 + b2 + h1@Wroot2); s = h2.u_rel; t = h2.u_root
__global__ void __launch_bounds__(256) k_gc2(const int* __restrict__ batch,
                                             const float* __restrict__ Wrel,
                                             const float* __restrict__ brel,
                                             const float* __restrict__ Wroot) {
    __shared__ float sw[HH * HH];    // 16 KB (Wrel then Wroot)
    __shared__ float st[64 * 68];    // 17.4 KB (agg stage then h1 stage)
    __shared__ float sb[HH], su[HH], sv[HH];
    __shared__ float binsT[GG];
    int t = threadIdx.x;
    int node0 = blockIdx.x * 64;
    {
        const float4* w4 = (const float4*)Wrel;
        float4* s4 = (float4*)sw;
        #pragma unroll
        for (int i = t; i < HH * HH / 4; i += 256) s4[i] = w4[i];
        if (t < HH) { sb[t] = brel[t]; su[t] = g_urel[t]; sv[t] = g_uroot[t]; }
        if (t < GG) binsT[t] = 0.f;
    }
    // gather agg2 rows: 8 warps x 8 nodes, warp reads 256B/edge coalesced
    {
        int w = t >> 5, lid = t & 31;
        int c2 = lid * 2;
        #pragma unroll
        for (int k = 0; k < 8; k++) {
            int ln = w * 8 + k;
            int node = node0 + ln;
            float ax = 0.f, ay = 0.f;
            if (node < NN) {
                int beg = g_off[node], end = g_off[node + 1];
                int j = beg;
                for (; j + 1 < end; j += 2) {
                    int s0 = g_srt[j], s1 = g_srt[j + 1];
                    float2 v0 = __ldg((const float2*)(g_h1 + (size_t)s0 * HH + c2));
                    float2 v1 = __ldg((const float2*)(g_h1 + (size_t)s1 * HH + c2));
                    ax += v0.x + v1.x;
                    ay += v0.y + v1.y;
                }
                if (j < end) {
                    float2 v0 = __ldg((const float2*)(g_h1 + (size_t)g_srt[j] * HH + c2));
                    ax += v0.x; ay += v0.y;
                }
            }
            *(float2*)&st[ln * 68 + c2] = make_float2(ax, ay);
        }
    }
    __syncthreads();
    int kg = t & 15, ng = t >> 4;
    int k0 = kg * 4, n0 = ng * 4;
    float acc[4][4];
    #pragma unroll
    for (int i = 0; i < 4; i++) {
        acc[i][0] = sb[k0]; acc[i][1] = sb[k0 + 1]; acc[i][2] = sb[k0 + 2]; acc[i][3] = sb[k0 + 3];
    }
    // pass 1: rel GEMM on gathered agg
    #pragma unroll 4
    for (int j = 0; j < HH; j++) {
        float4 wr = *(const float4*)&sw[j * HH + k0];
        #pragma unroll
        for (int i = 0; i < 4; i++) {
            float av = st[(n0 + i) * 68 + j];
            acc[i][0] = fmaf(av, wr.x, acc[i][0]);
            acc[i][1] = fmaf(av, wr.y, acc[i][1]);
            acc[i][2] = fmaf(av, wr.z, acc[i][2]);
            acc[i][3] = fmaf(av, wr.w, acc[i][3]);
        }
    }
    __syncthreads();
    // restage: Wroot into sw, h1 rows into st
    {
        const float4* w4 = (const float4*)Wroot;
        float4* s4 = (float4*)sw;
        #pragma unroll
        for (int i = t; i < HH * HH / 4; i += 256) s4[i] = w4[i];
        float4 z = make_float4(0.f, 0.f, 0.f, 0.f);
        float4* st4 = (float4*)st;
        #pragma unroll
        for (int idx = t; idx < 64 * 16; idx += 256) {
            int r = idx >> 4, q = idx & 15;
            float4 v = (node0 + r < NN) ? ((const float4*)(g_h1 + (size_t)(node0 + r) * HH))[q] : z;
            st4[r * 17 + q] = v;
        }
    }
    __syncthreads();
    // pass 2: root GEMM
    #pragma unroll 4
    for (int j = 0; j < HH; j++) {
        float4 wo = *(const float4*)&sw[j * HH + k0];
        #pragma unroll
        for (int i = 0; i < 4; i++) {
            float hv = st[(n0 + i) * 68 + j];
            acc[i][0] = fmaf(hv, wo.x, acc[i][0]);
            acc[i][1] = fmaf(hv, wo.y, acc[i][1]);
            acc[i][2] = fmaf(hv, wo.z, acc[i][2]);
            acc[i][3] = fmaf(hv, wo.w, acc[i][3]);
        }
    }
    // epilogue: relu, fold into per-node scalars, pool T
    float u0 = su[k0], u1 = su[k0 + 1], u2 = su[k0 + 2], u3 = su[k0 + 3];
    float v0 = sv[k0], v1 = sv[k0 + 1], v2 = sv[k0 + 2], v3 = sv[k0 + 3];
    #pragma unroll
    for (int i = 0; i < 4; i++) {
        float h0 = fmaxf(acc[i][0], 0.f);
        float h1 = fmaxf(acc[i][1], 0.f);
        float h2 = fmaxf(acc[i][2], 0.f);
        float h3 = fmaxf(acc[i][3], 0.f);
        float sp = h0 * u0 + h1 * u1 + h2 * u2 + h3 * u3;
        float tp = h0 * v0 + h1 * v1 + h2 * v2 + h3 * v3;
        #pragma unroll
        for (int off = 8; off > 0; off >>= 1) {
            sp += __shfl_down_sync(0xffffffffu, sp, off, 16);
            tp += __shfl_down_sync(0xffffffffu, tp, off, 16);
        }
        if (kg == 0) {
            int node = node0 + n0 + i;
            if (node < NN) {
                g_s[node] = sp;
                atomicAdd(&binsT[batch[node]], tp);
            }
        }
    }
    __syncthreads();
    if (t < GG && binsT[t] != 0.f) atomicAdd(&g_poolT[t], binsT[t]);
}

// ---------------- scalar edge scatter into per-graph pool ----------------
__global__ void __launch_bounds__(256) k_scatter3(const int* __restrict__ ei,
                                                  const int* __restrict__ batch) {
    __shared__ float bins[GG];
    int t = threadIdx.x;
    if (t < GG) bins[t] = 0.f;
    __syncthreads();
    int e = blockIdx.x * 256 + t;
    int src = ei[e];
    int dst = ei[EE + e];
    atomicAdd(&bins[batch[dst]], g_s[src]);
    __syncthreads();
    if (t < GG && bins[t] != 0.f) atomicAdd(&g_poolS[t], bins[t]);
}

// ---------------- finalize: mean pool; counts via binary search on sorted batch ----
__global__ void k_finalize(const int* __restrict__ batch, float* __restrict__ out) {
    int g = threadIdx.x;
    if (g < GG) {
        int lb0, lb1;
        { int lo = 0, hi = NN; while (lo < hi) { int m = (lo + hi) >> 1; if (batch[m] < g) lo = m + 1; else hi = m; } lb0 = lo; }
        { int lo = 0, hi = NN; while (lo < hi) { int m = (lo + hi) >> 1; if (batch[m] < g + 1) lo = m + 1; else hi = m; } lb1 = lo; }
        float c = (float)(lb1 - lb0);
        out[g] = (c > 0.f) ? (g_poolS[g] + g_poolT[g]) / c + g_e : 0.f;
    }
}

extern "C" void kernel_launch(void* const* d_in, const int* in_sizes, int n_in,
                              void* d_out, int out_size) {
    const float* x      = (const float*)d_in[0];
    const int*   ei     = (const int*)d_in[1];
    const int*   batch  = (const int*)d_in[2];
    const float* Wrel1  = (const float*)d_in[3];
    const float* brel1  = (const float*)d_in[4];
    const float* Wroot1 = (const float*)d_in[5];
    const float* Wrel2  = (const float*)d_in[6];
    const float* brel2  = (const float*)d_in[7];
    const float* Wroot2 = (const float*)d_in[8];
    const float* Wrel3  = (const float*)d_in[9];
    const float* brel3  = (const float*)d_in[10];
    const float* Wroot3 = (const float*)d_in[11];
    const float* c1w    = (const float*)d_in[12];
    const float* c1b    = (const float*)d_in[13];
    float* out = (float*)d_out;

    k_zero<<<(NN + 255) / 256, 256>>>();
    k_hist<<<EE / 256, 256>>>(ei);
    k_scan<<<1, 1024>>>();
    k_build<<<EE / 256, 256>>>(ei);
    k_coeffs<<<1, 64>>>(c1w, c1b, Wrel3, brel3, Wroot3);
    k_gc1<<<GRID_GC, 256>>>(x, Wrel1, brel1, Wroot1);
    k_gc2<<<GRID_GC, 256>>>(batch, Wrel2, brel2, Wroot2);
    k_scatter3<<<EE / 256, 256>>>(ei, batch);
    k_finalize<<<1, 128>>>(batch, out);
}

// round 4
// speedup vs baseline: 2.8587x; 1.7254x over previous
#include <cuda_runtime.h>

#define NN 50000
#define EE 800000
#define GG 128
#define FIN 16
#define HH 64
#define LL 63
#define GRID_GC ((NN + 63) / 64)
#define TILE 1024
#define NT ((NN + TILE - 1) / TILE)   // 49
#define E4 (EE / 4)                   // 200000
#define GRID_E4 ((E4 + 255) / 256)    // 782

// ---------------- scratch (device globals; no allocations) ----------------
__device__ int g_hist[NN];
__device__ int g_off[NN + 1];
__device__ int g_cursor[NN];
__device__ int g_srt[EE];
__device__ int g_bsum[NT];
__device__ int g_toff[NT];
__device__ __align__(16) float g_h1[NN * HH];
__device__ float g_s[NN];
__device__ float g_poolS[GG], g_poolT[GG];
__device__ float g_urel[HH], g_uroot[HH];
__device__ float g_e;

// ---------------- zero ----------------
__global__ void k_zero() {
    int i = blockIdx.x * 256 + threadIdx.x;
    if (i < NN) g_hist[i] = 0;
    if (i < GG) { g_poolS[i] = 0.f; g_poolT[i] = 0.f; }
}

// ---------------- histogram of dst (4 edges / thread) ----------------
__global__ void __launch_bounds__(256) k_hist(const int* __restrict__ ei) {
    int tid = blockIdx.x * 256 + threadIdx.x;
    if (tid < E4) {
        int4 d = ((const int4*)(ei + EE))[tid];
        atomicAdd(&g_hist[d.x], 1);
        atomicAdd(&g_hist[d.y], 1);
        atomicAdd(&g_hist[d.z], 1);
        atomicAdd(&g_hist[d.w], 1);
    }
}

// ---------------- tile reduce (49 blocks x 1024) ----------------
__global__ void __launch_bounds__(1024) k_reduceA() {
    int t = threadIdx.x;
    int i = blockIdx.x * TILE + t;
    int v = (i < NN) ? g_hist[i] : 0;
    #pragma unroll
    for (int d = 16; d > 0; d >>= 1) v += __shfl_down_sync(0xffffffffu, v, d);
    __shared__ int ws[32];
    if ((t & 31) == 0) ws[t >> 5] = v;
    __syncthreads();
    if (t < 32) {
        int s = ws[t];
        #pragma unroll
        for (int d = 16; d > 0; d >>= 1) s += __shfl_down_sync(0xffffffffu, s, d);
        if (t == 0) g_bsum[blockIdx.x] = s;
    }
}

// ---------------- small: block0 = scan of 49 tile sums; block1 = conv1d fold ------
__global__ void __launch_bounds__(64) k_small(const float* __restrict__ w, const float* __restrict__ b,
                                              const float* __restrict__ Wrel3, const float* __restrict__ brel3,
                                              const float* __restrict__ Wroot3) {
    int t = threadIdx.x;
    if (blockIdx.x == 0) {
        __shared__ int ss[64];
        int own = (t < NT) ? g_bsum[t] : 0;
        ss[t] = own;
        __syncthreads();
        #pragma unroll
        for (int d = 1; d < 64; d <<= 1) {
            int v = (t >= d) ? ss[t - d] : 0;
            __syncthreads();
            ss[t] += v;
            __syncthreads();
        }
        if (t < NT) g_toff[t] = ss[t] - own;
        if (t == NT - 1) g_off[NN] = ss[t];
    } else {
        __shared__ float c[HH];
        __shared__ float dsh;
        c[t] = (t == 0) ? 1.f : 0.f;
        float Ssum = 1.f, dacc = 0.f;
        __syncthreads();
        for (int i = LL - 1; i >= 0; --i) {
            float w0 = w[2 * i], w1 = w[2 * i + 1];
            float prev = (t > 0) ? c[t - 1] : 0.f;
            float cur = c[t];
            __syncthreads();
            c[t] = fmaf(w0, cur, w1 * prev);
            if (t == 0) { dacc += b[i] * Ssum; Ssum = (w0 + w1) * Ssum; }
            __syncthreads();
        }
        if (t == 0) dsh = dacc;
        __syncthreads();
        float ur = 0.f, uo = 0.f;
        #pragma unroll 4
        for (int k = 0; k < HH; k++) {
            ur += Wrel3[t * HH + k] * c[k];
            uo += Wroot3[t * HH + k] * c[k];
        }
        g_urel[t] = ur;
        g_uroot[t] = uo;
        if (t == 0) {
            float e = dsh;
            for (int k = 0; k < HH; k++) e += brel3[k] * c[k];
            g_e = e;
        }
    }
}

// ---------------- tile scan (49 blocks x 1024): off = exclusive prefix ----------------
__global__ void __launch_bounds__(1024) k_scanC() {
    int t = threadIdx.x;
    int lane = t & 31, wid = t >> 5;
    int i = blockIdx.x * TILE + t;
    int v = (i < NN) ? g_hist[i] : 0;
    int inc = v;
    #pragma unroll
    for (int d = 1; d < 32; d <<= 1) {
        int n = __shfl_up_sync(0xffffffffu, inc, d);
        if (lane >= d) inc += n;
    }
    __shared__ int ws[32];
    if (lane == 31) ws[wid] = inc;
    __syncthreads();
    if (wid == 0) {
        int s = ws[lane];
        int si = s;
        #pragma unroll
        for (int d = 1; d < 32; d <<= 1) {
            int n = __shfl_up_sync(0xffffffffu, si, d);
            if (lane >= d) si += n;
        }
        ws[lane] = si - s;
    }
    __syncthreads();
    if (i < NN) {
        int excl = inc - v + ws[wid] + g_toff[blockIdx.x];
        g_off[i] = excl;
        g_cursor[i] = excl;
    }
}

// ---------------- build sorted src list (4 edges / thread) ----------------
__global__ void __launch_bounds__(256) k_build(const int* __restrict__ ei) {
    int tid = blockIdx.x * 256 + threadIdx.x;
    if (tid < E4) {
        int4 s4 = ((const int4*)ei)[tid];
        int4 d4 = ((const int4*)(ei + EE))[tid];
        int p0 = atomicAdd(&g_cursor[d4.x], 1);
        int p1 = atomicAdd(&g_cursor[d4.y], 1);
        int p2 = atomicAdd(&g_cursor[d4.z], 1);
        int p3 = atomicAdd(&g_cursor[d4.w], 1);
        g_srt[p0] = s4.x;
        g_srt[p1] = s4.y;
        g_srt[p2] = s4.z;
        g_srt[p3] = s4.w;
    }
}

// ---------------- GC1 fused: agg = CSR-gather(x); h1 = relu(agg@Wrel1 + b + x@Wroot1) ----
__global__ void __launch_bounds__(256) k_gc1(const float* __restrict__ x,
                                             const float* __restrict__ Wrel,
                                             const float* __restrict__ brel,
                                             const float* __restrict__ Wroot) {
    __shared__ float swr[FIN * HH];
    __shared__ float swo[FIN * HH];
    __shared__ float sb[HH];
    __shared__ float sa[64 * 17];
    __shared__ float sx[64 * 20];
    __shared__ int sidx[8][32];
    int t = threadIdx.x;
    int node0 = blockIdx.x * 64;
    {
        const float4* wr4 = (const float4*)Wrel;
        const float4* wo4 = (const float4*)Wroot;
        float4* swr4 = (float4*)swr;
        float4* swo4 = (float4*)swo;
        if (t < FIN * HH / 4) { swr4[t] = wr4[t]; swo4[t] = wo4[t]; }
        if (t < HH) sb[t] = brel[t];
    }
    // stage root rows
    {
        float4 z = make_float4(0.f, 0.f, 0.f, 0.f);
        int r = t >> 2, q = t & 3;
        float4 v = (node0 + r < NN) ? ((const float4*)(x + (size_t)(node0 + r) * FIN))[q] : z;
        *(float4*)&sx[r * 20 + q * 4] = v;
    }
    // gather: warp per 8 nodes; staged indices + unrolled independent loads
    {
        int w = t >> 5, lane = t & 31;
        int col = lane & 15, half = lane >> 4;
        #pragma unroll
        for (int k = 0; k < 8; k++) {
            int ln = w * 8 + k;
            int node = node0 + ln;
            float acc = 0.f;
            if (node < NN) {
                int beg = g_off[node], end = g_off[node + 1];
                for (int base = beg; base < end; base += 32) {
                    int c = end - base; if (c > 32) c = 32;
                    if (lane < c) sidx[w][lane] = g_srt[base + lane];
                    __syncwarp();
                    int m = 0;
                    for (; m + 8 <= c; m += 8) {
                        int sA = sidx[w][m + half];
                        int sB = sidx[w][m + 2 + half];
                        int sC = sidx[w][m + 4 + half];
                        int sD = sidx[w][m + 6 + half];
                        float vA = __ldg(&x[(size_t)sA * FIN + col]);
                        float vB = __ldg(&x[(size_t)sB * FIN + col]);
                        float vC = __ldg(&x[(size_t)sC * FIN + col]);
                        float vD = __ldg(&x[(size_t)sD * FIN + col]);
                        acc += vA + vB + vC + vD;
                    }
                    for (; m + 2 <= c; m += 2)
                        acc += __ldg(&x[(size_t)sidx[w][m + half] * FIN + col]);
                    if (m < c && half == 0)
                        acc += __ldg(&x[(size_t)sidx[w][m] * FIN + col]);
                    __syncwarp();
                }
            }
            acc += __shfl_down_sync(0xffffffffu, acc, 16);
            if (lane < 16) sa[ln * 17 + col] = acc;
        }
    }
    __syncthreads();
    int kg = t & 15, ng = t >> 4;
    int k0 = kg * 4, n0 = ng * 4;
    float acc[4][4];
    #pragma unroll
    for (int i = 0; i < 4; i++) {
        acc[i][0] = sb[k0]; acc[i][1] = sb[k0 + 1]; acc[i][2] = sb[k0 + 2]; acc[i][3] = sb[k0 + 3];
    }
    #pragma unroll
    for (int j = 0; j < FIN; j++) {
        float4 wr = *(const float4*)&swr[j * HH + k0];
        float4 wo = *(const float4*)&swo[j * HH + k0];
        #pragma unroll
        for (int i = 0; i < 4; i++) {
            float av = sa[(n0 + i) * 17 + j];
            float xv = sx[(n0 + i) * 20 + j];
            acc[i][0] = fmaf(av, wr.x, fmaf(xv, wo.x, acc[i][0]));
            acc[i][1] = fmaf(av, wr.y, fmaf(xv, wo.y, acc[i][1]));
            acc[i][2] = fmaf(av, wr.z, fmaf(xv, wo.z, acc[i][2]));
            acc[i][3] = fmaf(av, wr.w, fmaf(xv, wo.w, acc[i][3]));
        }
    }
    #pragma unroll
    for (int i = 0; i < 4; i++) {
        int node = node0 + n0 + i;
        if (node < NN) {
            float4 o;
            o.x = fmaxf(acc[i][0], 0.f);
            o.y = fmaxf(acc[i][1], 0.f);
            o.z = fmaxf(acc[i][2], 0.f);
            o.w = fmaxf(acc[i][3], 0.f);
            *(float4*)&g_h1[(size_t)node * HH + k0] = o;
        }
    }
}

// ---------------- GC2 fused (two-pass shared buffer) + folded layer 3 -------------
__global__ void __launch_bounds__(256) k_gc2(const int* __restrict__ batch,
                                             const float* __restrict__ Wrel,
                                             const float* __restrict__ brel,
                                             const float* __restrict__ Wroot) {
    __shared__ float sw[HH * HH];
    __shared__ float st[64 * 68];
    __shared__ float sb[HH], su[HH], sv[HH];
    __shared__ float binsT[GG];
    __shared__ int sidx[8][32];
    int t = threadIdx.x;
    int node0 = blockIdx.x * 64;
    {
        const float4* w4 = (const float4*)Wrel;
        float4* s4 = (float4*)sw;
        #pragma unroll
        for (int i = t; i < HH * HH / 4; i += 256) s4[i] = w4[i];
        if (t < HH) { sb[t] = brel[t]; su[t] = g_urel[t]; sv[t] = g_uroot[t]; }
        if (t < GG) binsT[t] = 0.f;
    }
    // gather agg2 rows: warp per 8 nodes; staged indices + unrolled loads
    {
        int w = t >> 5, lane = t & 31;
        int c2 = lane * 2;
        #pragma unroll
        for (int k = 0; k < 8; k++) {
            int ln = w * 8 + k;
            int node = node0 + ln;
            float ax = 0.f, ay = 0.f;
            if (node < NN) {
                int beg = g_off[node], end = g_off[node + 1];
                for (int base = beg; base < end; base += 32) {
                    int c = end - base; if (c > 32) c = 32;
                    if (lane < c) sidx[w][lane] = g_srt[base + lane];
                    __syncwarp();
                    int m = 0;
                    for (; m + 4 <= c; m += 4) {
                        int s0 = sidx[w][m], s1 = sidx[w][m + 1];
                        int s2 = sidx[w][m + 2], s3 = sidx[w][m + 3];
                        float2 v0 = __ldg((const float2*)(g_h1 + (size_t)s0 * HH + c2));
                        float2 v1 = __ldg((const float2*)(g_h1 + (size_t)s1 * HH + c2));
                        float2 v2 = __ldg((const float2*)(g_h1 + (size_t)s2 * HH + c2));
                        float2 v3 = __ldg((const float2*)(g_h1 + (size_t)s3 * HH + c2));
                        ax += v0.x + v1.x + v2.x + v3.x;
                        ay += v0.y + v1.y + v2.y + v3.y;
                    }
                    for (; m < c; m++) {
                        float2 v0 = __ldg((const float2*)(g_h1 + (size_t)sidx[w][m] * HH + c2));
                        ax += v0.x; ay += v0.y;
                    }
                    __syncwarp();
                }
            }
            *(float2*)&st[ln * 68 + c2] = make_float2(ax, ay);
        }
    }
    __syncthreads();
    int kg = t & 15, ng = t >> 4;
    int k0 = kg * 4, n0 = ng * 4;
    float acc[4][4];
    #pragma unroll
    for (int i = 0; i < 4; i++) {
        acc[i][0] = sb[k0]; acc[i][1] = sb[k0 + 1]; acc[i][2] = sb[k0 + 2]; acc[i][3] = sb[k0 + 3];
    }
    // pass 1: rel GEMM on gathered agg
    #pragma unroll 4
    for (int j = 0; j < HH; j++) {
        float4 wr = *(const float4*)&sw[j * HH + k0];
        #pragma unroll
        for (int i = 0; i < 4; i++) {
            float av = st[(n0 + i) * 68 + j];
            acc[i][0] = fmaf(av, wr.x, acc[i][0]);
            acc[i][1] = fmaf(av, wr.y, acc[i][1]);
            acc[i][2] = fmaf(av, wr.z, acc[i][2]);
            acc[i][3] = fmaf(av, wr.w, acc[i][3]);
        }
    }
    __syncthreads();
    // restage: Wroot into sw, h1 rows into st
    {
        const float4* w4 = (const float4*)Wroot;
        float4* s4 = (float4*)sw;
        #pragma unroll
        for (int i = t; i < HH * HH / 4; i += 256) s4[i] = w4[i];
        float4 z = make_float4(0.f, 0.f, 0.f, 0.f);
        float4* st4 = (float4*)st;
        #pragma unroll
        for (int idx = t; idx < 64 * 16; idx += 256) {
            int r = idx >> 4, q = idx & 15;
            float4 v = (node0 + r < NN) ? ((const float4*)(g_h1 + (size_t)(node0 + r) * HH))[q] : z;
            st4[r * 17 + q] = v;
        }
    }
    __syncthreads();
    // pass 2: root GEMM
    #pragma unroll 4
    for (int j = 0; j < HH; j++) {
        float4 wo = *(const float4*)&sw[j * HH + k0];
        #pragma unroll
        for (int i = 0; i < 4; i++) {
            float hv = st[(n0 + i) * 68 + j];
            acc[i][0] = fmaf(hv, wo.x, acc[i][0]);
            acc[i][1] = fmaf(hv, wo.y, acc[i][1]);
            acc[i][2] = fmaf(hv, wo.z, acc[i][2]);
            acc[i][3] = fmaf(hv, wo.w, acc[i][3]);
        }
    }
    // epilogue: relu, fold into per-node scalars, pool T
    float u0 = su[k0], u1 = su[k0 + 1], u2 = su[k0 + 2], u3 = su[k0 + 3];
    float v0 = sv[k0], v1 = sv[k0 + 1], v2 = sv[k0 + 2], v3 = sv[k0 + 3];
    #pragma unroll
    for (int i = 0; i < 4; i++) {
        float h0 = fmaxf(acc[i][0], 0.f);
        float h1 = fmaxf(acc[i][1], 0.f);
        float h2 = fmaxf(acc[i][2], 0.f);
        float h3 = fmaxf(acc[i][3], 0.f);
        float sp = h0 * u0 + h1 * u1 + h2 * u2 + h3 * u3;
        float tp = h0 * v0 + h1 * v1 + h2 * v2 + h3 * v3;
        #pragma unroll
        for (int off = 8; off > 0; off >>= 1) {
            sp += __shfl_down_sync(0xffffffffu, sp, off, 16);
            tp += __shfl_down_sync(0xffffffffu, tp, off, 16);
        }
        if (kg == 0) {
            int node = node0 + n0 + i;
            if (node < NN) {
                g_s[node] = sp;
                atomicAdd(&binsT[batch[node]], tp);
            }
        }
    }
    __syncthreads();
    if (t < GG && binsT[t] != 0.f) atomicAdd(&g_poolT[t], binsT[t]);
}

// ---------------- scalar edge scatter into per-graph pool (4 edges / thread) ------
__global__ void __launch_bounds__(256) k_scatter3(const int* __restrict__ ei,
                                                  const int* __restrict__ batch) {
    __shared__ float bins[GG];
    int t = threadIdx.x;
    if (t < GG) bins[t] = 0.f;
    __syncthreads();
    int tid = blockIdx.x * 256 + t;
    if (tid < E4) {
        int4 s4 = ((const int4*)ei)[tid];
        int4 d4 = ((const int4*)(ei + EE))[tid];
        float v0 = g_s[s4.x], v1 = g_s[s4.y], v2 = g_s[s4.z], v3 = g_s[s4.w];
        int b0 = batch[d4.x], b1 = batch[d4.y], b2 = batch[d4.z], b3 = batch[d4.w];
        atomicAdd(&bins[b0], v0);
        atomicAdd(&bins[b1], v1);
        atomicAdd(&bins[b2], v2);
        atomicAdd(&bins[b3], v3);
    }
    __syncthreads();
    if (t < GG && bins[t] != 0.f) atomicAdd(&g_poolS[t], bins[t]);
}

// ---------------- finalize: mean pool; counts via binary search on sorted batch ----
__global__ void k_finalize(const int* __restrict__ batch, float* __restrict__ out) {
    int g = threadIdx.x;
    if (g < GG) {
        int lb0, lb1;
        { int lo = 0, hi = NN; while (lo < hi) { int m = (lo + hi) >> 1; if (batch[m] < g) lo = m + 1; else hi = m; } lb0 = lo; }
        { int lo = 0, hi = NN; while (lo < hi) { int m = (lo + hi) >> 1; if (batch[m] < g + 1) lo = m + 1; else hi = m; } lb1 = lo; }
        float c = (float)(lb1 - lb0);
        out[g] = (c > 0.f) ? (g_poolS[g] + g_poolT[g]) / c + g_e : 0.f;
    }
}

extern "C" void kernel_launch(void* const* d_in, const int* in_sizes, int n_in,
                              void* d_out, int out_size) {
    const float* x      = (const float*)d_in[0];
    const int*   ei     = (const int*)d_in[1];
    const int*   batch  = (const int*)d_in[2];
    const float* Wrel1  = (const float*)d_in[3];
    const float* brel1  = (const float*)d_in[4];
    const float* Wroot1 = (const float*)d_in[5];
    const float* Wrel2  = (const float*)d_in[6];
    const float* brel2  = (const float*)d_in[7];
    const float* Wroot2 = (const float*)d_in[8];
    const float* Wrel3  = (const float*)d_in[9];
    const float* brel3  = (const float*)d_in[10];
    const float* Wroot3 = (const float*)d_in[11];
    const float* c1w    = (const float*)d_in[12];
    const float* c1b    = (const float*)d_in[13];
    float* out = (float*)d_out;

    k_zero<<<(NN + 255) / 256, 256>>>();
    k_hist<<<GRID_E4, 256>>>(ei);
    k_reduceA<<<NT, 1024>>>();
    k_small<<<2, 64>>>(c1w, c1b, Wrel3, brel3, Wroot3);
    k_scanC<<<NT, 1024>>>();
    k_build<<<GRID_E4, 256>>>(ei);
    k_gc1<<<GRID_GC, 256>>>(x, Wrel1, brel1, Wroot1);
    k_gc2<<<GRID_GC, 256>>>(batch, Wrel2, brel2, Wroot2);
    k_scatter3<<<GRID_E4, 256>>>(ei, batch);
    k_finalize<<<1, 128>>>(batch, out);
}

// round 5
// speedup vs baseline: 2.9521x; 1.0327x over previous
#include <cuda_runtime.h>

#define NN 50000
#define EE 800000
#define GG 128
#define FIN 16
#define HH 64
#define LL 63
#define GRID_GC ((NN + 63) / 64)
#define TILE 1024
#define NT ((NN + TILE - 1) / TILE)   // 49
#define E4 (EE / 4)                   // 200000
#define GRID_E4 ((E4 + 255) / 256)    // 782

// ---------------- scratch (device globals; no allocations) ----------------
__device__ int g_hist[NN];
__device__ int g_off[NN + 1];
__device__ int g_cursor[NN];
__device__ int g_srt[EE];
__device__ int g_bsum[NT];
__device__ __align__(16) float g_h1[NN * HH];
__device__ float g_s[NN];
__device__ float g_poolS[GG], g_poolT[GG];
__device__ float g_urel[HH], g_uroot[HH];
__device__ float g_e;

// ---------------- zero ----------------
__global__ void k_zero() {
    int i = blockIdx.x * 256 + threadIdx.x;
    if (i < NN) g_hist[i] = 0;
    if (i < GG) { g_poolS[i] = 0.f; g_poolT[i] = 0.f; }
    if (i == 0) g_off[NN] = EE;
}

// ---------------- histogram of dst (4 edges / thread) ----------------
__global__ void __launch_bounds__(256) k_hist(const int* __restrict__ ei) {
    int tid = blockIdx.x * 256 + threadIdx.x;
    if (tid < E4) {
        int4 d = ((const int4*)(ei + EE))[tid];
        atomicAdd(&g_hist[d.x], 1);
        atomicAdd(&g_hist[d.y], 1);
        atomicAdd(&g_hist[d.z], 1);
        atomicAdd(&g_hist[d.w], 1);
    }
}

// ---------------- tile reduce (blocks 0..NT-1) + conv1d fold (block NT) ----------------
__global__ void __launch_bounds__(1024) k_reduceA(const float* __restrict__ w, const float* __restrict__ b,
                                                  const float* __restrict__ Wrel3, const float* __restrict__ brel3,
                                                  const float* __restrict__ Wroot3) {
    int t = threadIdx.x;
    if (blockIdx.x < NT) {
        int i = blockIdx.x * TILE + t;
        int v = (i < NN) ? g_hist[i] : 0;
        #pragma unroll
        for (int d = 16; d > 0; d >>= 1) v += __shfl_down_sync(0xffffffffu, v, d);
        __shared__ int ws[32];
        if ((t & 31) == 0) ws[t >> 5] = v;
        __syncthreads();
        if (t < 32) {
            int s = ws[t];
            #pragma unroll
            for (int d = 16; d > 0; d >>= 1) s += __shfl_down_sync(0xffffffffu, s, d);
            if (t == 0) g_bsum[blockIdx.x] = s;
        }
        return;
    }
    // block NT: fold 63 Conv1d layers + GraphConv3 weights into (u_rel, u_root, e)
    __shared__ float swb[2 * LL + LL];   // w[126], b[63]
    __shared__ float sc[HH];
    if (t < 2 * LL) swb[t] = w[t];
    else if (t < 3 * LL) swb[t] = b[t - 2 * LL];
    __syncthreads();
    float dacc = 0.f;
    if (t < 32) {
        // lane t holds c[2t], c[2t+1]; recurrence c'[k] = w0*c[k] + w1*c[k-1]
        float clo = (t == 0) ? 1.f : 0.f, chi = 0.f;
        float Ssum = 1.f;
        #pragma unroll 1
        for (int i = LL - 1; i >= 0; --i) {
            float w0 = swb[2 * i], w1 = swb[2 * i + 1];
            dacc = fmaf(swb[2 * LL + i], Ssum, dacc);
            Ssum *= (w0 + w1);
            float ph = __shfl_up_sync(0xffffffffu, chi, 1);
            if (t == 0) ph = 0.f;
            float nlo = fmaf(w0, clo, w1 * ph);
            float nhi = fmaf(w0, chi, w1 * clo);
            clo = nlo; chi = nhi;
        }
        sc[2 * t] = clo;
        sc[2 * t + 1] = chi;
    }
    __syncthreads();
    if (t < HH) {
        float ur = 0.f, uo = 0.f;
        #pragma unroll 8
        for (int k = 0; k < HH; k++) {
            ur = fmaf(Wrel3[t * HH + k], sc[k], ur);
            uo = fmaf(Wroot3[t * HH + k], sc[k], uo);
        }
        g_urel[t] = ur;
        g_uroot[t] = uo;
    }
    if (t == 0) {
        float e = dacc;
        #pragma unroll 8
        for (int k = 0; k < HH; k++) e = fmaf(brel3[k], sc[k], e);
        g_e = e;
    }
}

// ---------------- tile scan: off = exclusive prefix (toff computed in-block) --------
__global__ void __launch_bounds__(1024) k_scanC() {
    __shared__ int ws[32];
    __shared__ int stoff;
    int t = threadIdx.x;
    int lane = t & 31, wid = t >> 5;
    int i = blockIdx.x * TILE + t;
    int v = (i < NN) ? g_hist[i] : 0;
    int inc = v;
    #pragma unroll
    for (int d = 1; d < 32; d <<= 1) {
        int n = __shfl_up_sync(0xffffffffu, inc, d);
        if (lane >= d) inc += n;
    }
    if (lane == 31) ws[wid] = inc;
    if (wid == 1) {  // warp 1: this block's tile offset = sum of preceding tile sums
        int B = blockIdx.x;
        int s = (lane < B) ? g_bsum[lane] : 0;
        if (lane + 32 < B) s += g_bsum[lane + 32];
        #pragma unroll
        for (int d = 16; d > 0; d >>= 1) s += __shfl_down_sync(0xffffffffu, s, d);
        if (lane == 0) stoff = s;
    }
    __syncthreads();
    if (wid == 0) {
        int s = ws[lane];
        int si = s;
        #pragma unroll
        for (int d = 1; d < 32; d <<= 1) {
            int n = __shfl_up_sync(0xffffffffu, si, d);
            if (lane >= d) si += n;
        }
        ws[lane] = si - s;
    }
    __syncthreads();
    if (i < NN) {
        int excl = inc - v + ws[wid] + stoff;
        g_off[i] = excl;
        g_cursor[i] = excl;
    }
}

// ---------------- build sorted src list (4 edges / thread) ----------------
__global__ void __launch_bounds__(256) k_build(const int* __restrict__ ei) {
    int tid = blockIdx.x * 256 + threadIdx.x;
    if (tid < E4) {
        int4 s4 = ((const int4*)ei)[tid];
        int4 d4 = ((const int4*)(ei + EE))[tid];
        int p0 = atomicAdd(&g_cursor[d4.x], 1);
        int p1 = atomicAdd(&g_cursor[d4.y], 1);
        int p2 = atomicAdd(&g_cursor[d4.z], 1);
        int p3 = atomicAdd(&g_cursor[d4.w], 1);
        g_srt[p0] = s4.x;
        g_srt[p1] = s4.y;
        g_srt[p2] = s4.z;
        g_srt[p3] = s4.w;
    }
}

// ---------------- GC1 fused: agg = CSR-gather(x); h1 = relu(agg@Wrel1 + b + x@Wroot1) ----
__global__ void __launch_bounds__(256) k_gc1(const float* __restrict__ x,
                                             const float* __restrict__ Wrel,
                                             const float* __restrict__ brel,
                                             const float* __restrict__ Wroot) {
    __shared__ float swr[FIN * HH];
    __shared__ float swo[FIN * HH];
    __shared__ float sb[HH];
    __shared__ float sa[64 * 17];
    __shared__ float sx[64 * 20];
    __shared__ int sidx[8][32];
    int t = threadIdx.x;
    int node0 = blockIdx.x * 64;
    {
        const float4* wr4 = (const float4*)Wrel;
        const float4* wo4 = (const float4*)Wroot;
        float4* swr4 = (float4*)swr;
        float4* swo4 = (float4*)swo;
        if (t < FIN * HH / 4) { swr4[t] = wr4[t]; swo4[t] = wo4[t]; }
        if (t < HH) sb[t] = brel[t];
    }
    // stage root rows
    {
        float4 z = make_float4(0.f, 0.f, 0.f, 0.f);
        int r = t >> 2, q = t & 3;
        float4 v = (node0 + r < NN) ? ((const float4*)(x + (size_t)(node0 + r) * FIN))[q] : z;
        *(float4*)&sx[r * 20 + q * 4] = v;
    }
    // gather: warp per 8 nodes; staged indices + unrolled independent loads
    {
        int w = t >> 5, lane = t & 31;
        int col = lane & 15, half = lane >> 4;
        #pragma unroll
        for (int k = 0; k < 8; k++) {
            int ln = w * 8 + k;
            int node = node0 + ln;
            float acc = 0.f;
            if (node < NN) {
                int beg = g_off[node], end = g_off[node + 1];
                for (int base = beg; base < end; base += 32) {
                    int c = end - base; if (c > 32) c = 32;
                    if (lane < c) sidx[w][lane] = g_srt[base + lane];
                    __syncwarp();
                    int m = 0;
                    for (; m + 8 <= c; m += 8) {
                        int sA = sidx[w][m + half];
                        int sB = sidx[w][m + 2 + half];
                        int sC = sidx[w][m + 4 + half];
                        int sD = sidx[w][m + 6 + half];
                        float vA = __ldg(&x[(size_t)sA * FIN + col]);
                        float vB = __ldg(&x[(size_t)sB * FIN + col]);
                        float vC = __ldg(&x[(size_t)sC * FIN + col]);
                        float vD = __ldg(&x[(size_t)sD * FIN + col]);
                        acc += vA + vB + vC + vD;
                    }
                    for (; m + 2 <= c; m += 2)
                        acc += __ldg(&x[(size_t)sidx[w][m + half] * FIN + col]);
                    if (m < c && half == 0)
                        acc += __ldg(&x[(size_t)sidx[w][m] * FIN + col]);
                    __syncwarp();
                }
            }
            acc += __shfl_down_sync(0xffffffffu, acc, 16);
            if (lane < 16) sa[ln * 17 + col] = acc;
        }
    }
    __syncthreads();
    int kg = t & 15, ng = t >> 4;
    int k0 = kg * 4, n0 = ng * 4;
    float acc[4][4];
    #pragma unroll
    for (int i = 0; i < 4; i++) {
        acc[i][0] = sb[k0]; acc[i][1] = sb[k0 + 1]; acc[i][2] = sb[k0 + 2]; acc[i][3] = sb[k0 + 3];
    }
    #pragma unroll
    for (int j = 0; j < FIN; j++) {
        float4 wr = *(const float4*)&swr[j * HH + k0];
        float4 wo = *(const float4*)&swo[j * HH + k0];
        #pragma unroll
        for (int i = 0; i < 4; i++) {
            float av = sa[(n0 + i) * 17 + j];
            float xv = sx[(n0 + i) * 20 + j];
            acc[i][0] = fmaf(av, wr.x, fmaf(xv, wo.x, acc[i][0]));
            acc[i][1] = fmaf(av, wr.y, fmaf(xv, wo.y, acc[i][1]));
            acc[i][2] = fmaf(av, wr.z, fmaf(xv, wo.z, acc[i][2]));
            acc[i][3] = fmaf(av, wr.w, fmaf(xv, wo.w, acc[i][3]));
        }
    }
    #pragma unroll
    for (int i = 0; i < 4; i++) {
        int node = node0 + n0 + i;
        if (node < NN) {
            float4 o;
            o.x = fmaxf(acc[i][0], 0.f);
            o.y = fmaxf(acc[i][1], 0.f);
            o.z = fmaxf(acc[i][2], 0.f);
            o.w = fmaxf(acc[i][3], 0.f);
            *(float4*)&g_h1[(size_t)node * HH + k0] = o;
        }
    }
}

// ---------------- GC2 fused (two-pass shared buffer) + folded layer 3 -------------
__global__ void __launch_bounds__(256) k_gc2(const int* __restrict__ batch,
                                             const float* __restrict__ Wrel,
                                             const float* __restrict__ brel,
                                             const float* __restrict__ Wroot) {
    __shared__ float sw[HH * HH];
    __shared__ float st[64 * 68];
    __shared__ float sb[HH], su[HH], sv[HH];
    __shared__ float binsT[GG];
    __shared__ int sidx[8][32];
    int t = threadIdx.x;
    int node0 = blockIdx.x * 64;
    {
        const float4* w4 = (const float4*)Wrel;
        float4* s4 = (float4*)sw;
        #pragma unroll
        for (int i = t; i < HH * HH / 4; i += 256) s4[i] = w4[i];
        if (t < HH) { sb[t] = brel[t]; su[t] = g_urel[t]; sv[t] = g_uroot[t]; }
        if (t < GG) binsT[t] = 0.f;
    }
    // gather agg2 rows: warp per 8 nodes; staged indices + unrolled loads
    {
        int w = t >> 5, lane = t & 31;
        int c2 = lane * 2;
        #pragma unroll
        for (int k = 0; k < 8; k++) {
            int ln = w * 8 + k;
            int node = node0 + ln;
            float ax = 0.f, ay = 0.f;
            if (node < NN) {
                int beg = g_off[node], end = g_off[node + 1];
                for (int base = beg; base < end; base += 32) {
                    int c = end - base; if (c > 32) c = 32;
                    if (lane < c) sidx[w][lane] = g_srt[base + lane];
                    __syncwarp();
                    int m = 0;
                    for (; m + 4 <= c; m += 4) {
                        int s0 = sidx[w][m], s1 = sidx[w][m + 1];
                        int s2 = sidx[w][m + 2], s3 = sidx[w][m + 3];
                        float2 v0 = __ldg((const float2*)(g_h1 + (size_t)s0 * HH + c2));
                        float2 v1 = __ldg((const float2*)(g_h1 + (size_t)s1 * HH + c2));
                        float2 v2 = __ldg((const float2*)(g_h1 + (size_t)s2 * HH + c2));
                        float2 v3 = __ldg((const float2*)(g_h1 + (size_t)s3 * HH + c2));
                        ax += v0.x + v1.x + v2.x + v3.x;
                        ay += v0.y + v1.y + v2.y + v3.y;
                    }
                    for (; m < c; m++) {
                        float2 v0 = __ldg((const float2*)(g_h1 + (size_t)sidx[w][m] * HH + c2));
                        ax += v0.x; ay += v0.y;
                    }
                    __syncwarp();
                }
            }
            *(float2*)&st[ln * 68 + c2] = make_float2(ax, ay);
        }
    }
    __syncthreads();
    int kg = t & 15, ng = t >> 4;
    int k0 = kg * 4, n0 = ng * 4;
    float acc[4][4];
    #pragma unroll
    for (int i = 0; i < 4; i++) {
        acc[i][0] = sb[k0]; acc[i][1] = sb[k0 + 1]; acc[i][2] = sb[k0 + 2]; acc[i][3] = sb[k0 + 3];
    }
    // pass 1: rel GEMM on gathered agg
    #pragma unroll 4
    for (int j = 0; j < HH; j++) {
        float4 wr = *(const float4*)&sw[j * HH + k0];
        #pragma unroll
        for (int i = 0; i < 4; i++) {
            float av = st[(n0 + i) * 68 + j];
            acc[i][0] = fmaf(av, wr.x, acc[i][0]);
            acc[i][1] = fmaf(av, wr.y, acc[i][1]);
            acc[i][2] = fmaf(av, wr.z, acc[i][2]);
            acc[i][3] = fmaf(av, wr.w, acc[i][3]);
        }
    }
    __syncthreads();
    // restage: Wroot into sw, h1 rows into st
    {
        const float4* w4 = (const float4*)Wroot;
        float4* s4 = (float4*)sw;
        #pragma unroll
        for (int i = t; i < HH * HH / 4; i += 256) s4[i] = w4[i];
        float4 z = make_float4(0.f, 0.f, 0.f, 0.f);
        float4* st4 = (float4*)st;
        #pragma unroll
        for (int idx = t; idx < 64 * 16; idx += 256) {
            int r = idx >> 4, q = idx & 15;
            float4 v = (node0 + r < NN) ? ((const float4*)(g_h1 + (size_t)(node0 + r) * HH))[q] : z;
            st4[r * 17 + q] = v;
        }
    }
    __syncthreads();
    // pass 2: root GEMM
    #pragma unroll 4
    for (int j = 0; j < HH; j++) {
        float4 wo = *(const float4*)&sw[j * HH + k0];
        #pragma unroll
        for (int i = 0; i < 4; i++) {
            float hv = st[(n0 + i) * 68 + j];
            acc[i][0] = fmaf(hv, wo.x, acc[i][0]);
            acc[i][1] = fmaf(hv, wo.y, acc[i][1]);
            acc[i][2] = fmaf(hv, wo.z, acc[i][2]);
            acc[i][3] = fmaf(hv, wo.w, acc[i][3]);
        }
    }
    // epilogue: relu, fold into per-node scalars, pool T
    float u0 = su[k0], u1 = su[k0 + 1], u2 = su[k0 + 2], u3 = su[k0 + 3];
    float v0 = sv[k0], v1 = sv[k0 + 1], v2 = sv[k0 + 2], v3 = sv[k0 + 3];
    #pragma unroll
    for (int i = 0; i < 4; i++) {
        float h0 = fmaxf(acc[i][0], 0.f);
        float h1 = fmaxf(acc[i][1], 0.f);
        float h2 = fmaxf(acc[i][2], 0.f);
        float h3 = fmaxf(acc[i][3], 0.f);
        float sp = h0 * u0 + h1 * u1 + h2 * u2 + h3 * u3;
        float tp = h0 * v0 + h1 * v1 + h2 * v2 + h3 * v3;
        #pragma unroll
        for (int off = 8; off > 0; off >>= 1) {
            sp += __shfl_down_sync(0xffffffffu, sp, off, 16);
            tp += __shfl_down_sync(0xffffffffu, tp, off, 16);
        }
        if (kg == 0) {
            int node = node0 + n0 + i;
            if (node < NN) {
                g_s[node] = sp;
                atomicAdd(&binsT[batch[node]], tp);
            }
        }
    }
    __syncthreads();
    if (t < GG && binsT[t] != 0.f) atomicAdd(&g_poolT[t], binsT[t]);
}

// ---------------- scalar edge scatter into per-graph pool (4 edges / thread) ------
__global__ void __launch_bounds__(256) k_scatter3(const int* __restrict__ ei,
                                                  const int* __restrict__ batch) {
    __shared__ float bins[GG];
    int t = threadIdx.x;
    if (t < GG) bins[t] = 0.f;
    __syncthreads();
    int tid = blockIdx.x * 256 + t;
    if (tid < E4) {
        int4 s4 = ((const int4*)ei)[tid];
        int4 d4 = ((const int4*)(ei + EE))[tid];
        float v0 = g_s[s4.x], v1 = g_s[s4.y], v2 = g_s[s4.z], v3 = g_s[s4.w];
        int b0 = batch[d4.x], b1 = batch[d4.y], b2 = batch[d4.z], b3 = batch[d4.w];
        atomicAdd(&bins[b0], v0);
        atomicAdd(&bins[b1], v1);
        atomicAdd(&bins[b2], v2);
        atomicAdd(&bins[b3], v3);
    }
    __syncthreads();
    if (t < GG && bins[t] != 0.f) atomicAdd(&g_poolS[t], bins[t]);
}

// ---------------- finalize: mean pool; counts via binary search on sorted batch ----
__global__ void k_finalize(const int* __restrict__ batch, float* __restrict__ out) {
    int g = threadIdx.x;
    if (g < GG) {
        int lb0, lb1;
        { int lo = 0, hi = NN; while (lo < hi) { int m = (lo + hi) >> 1; if (batch[m] < g) lo = m + 1; else hi = m; } lb0 = lo; }
        { int lo = 0, hi = NN; while (lo < hi) { int m = (lo + hi) >> 1; if (batch[m] < g + 1) lo = m + 1; else hi = m; } lb1 = lo; }
        float c = (float)(lb1 - lb0);
        out[g] = (c > 0.f) ? (g_poolS[g] + g_poolT[g]) / c + g_e : 0.f;
    }
}

extern "C" void kernel_launch(void* const* d_in, const int* in_sizes, int n_in,
                              void* d_out, int out_size) {
    const float* x      = (const float*)d_in[0];
    const int*   ei     = (const int*)d_in[1];
    const int*   batch  = (const int*)d_in[2];
    const float* Wrel1  = (const float*)d_in[3];
    const float* brel1  = (const float*)d_in[4];
    const float* Wroot1 = (const float*)d_in[5];
    const float* Wrel2  = (const float*)d_in[6];
    const float* brel2  = (const float*)d_in[7];
    const float* Wroot2 = (const float*)d_in[8];
    const float* Wrel3  = (const float*)d_in[9];
    const float* brel3  = (const float*)d_in[10];
    const float* Wroot3 = (const float*)d_in[11];
    const float* c1w    = (const float*)d_in[12];
    const float* c1b    = (const float*)d_in[13];
    float* out = (float*)d_out;

    k_zero<<<(NN + 255) / 256, 256>>>();
    k_hist<<<GRID_E4, 256>>>(ei);
    k_reduceA<<<NT + 1, 1024>>>(c1w, c1b, Wrel3, brel3, Wroot3);
    k_scanC<<<NT, 1024>>>();
    k_build<<<GRID_E4, 256>>>(ei);
    k_gc1<<<GRID_GC, 256>>>(x, Wrel1, brel1, Wroot1);
    k_gc2<<<GRID_GC, 256>>>(batch, Wrel2, brel2, Wroot2);
    k_scatter3<<<GRID_E4, 256>>>(ei, batch);
    k_finalize<<<1, 128>>>(batch, out);
}